// round 1
// baseline (speedup 1.0000x reference)
#include <cuda_runtime.h>
#include <cuda_bf16.h>

// Problem: out[p,o] = sum_d x[p,d]*(W[d,o] + eps[p,d,o]) + bias[o] + bias_eps[p,o]
// P=1024, D=512, O=512, all fp32.
// Bottleneck: streaming weight_eps (1.07 GB) once from HBM. ~150us floor at ~7.2TB/s.

#define PP 1024
#define DD 512
#define OO 512

// ---------------------------------------------------------------------------
// Kernel A: base GEMM  out = x @ W + bias + bias_eps
// 64x64 tile, BK=16, 256 threads, 4x4 micro-tile per thread.
// ---------------------------------------------------------------------------
__global__ __launch_bounds__(256)
void nes_base_gemm(const float* __restrict__ x,
                   const float* __restrict__ w,
                   const float* __restrict__ bias,
                   const float* __restrict__ bias_eps,
                   float* __restrict__ out) {
    __shared__ float As[16][64];   // [k][m]
    __shared__ float Bs[16][64];   // [k][n]

    const int tid = threadIdx.x;
    const int bm = blockIdx.y * 64;   // p-tile
    const int bn = blockIdx.x * 64;   // o-tile
    const int tx = tid & 15;          // n-group
    const int ty = tid >> 4;          // m-group

    float acc[4][4];
    #pragma unroll
    for (int i = 0; i < 4; i++)
        #pragma unroll
        for (int j = 0; j < 4; j++) acc[i][j] = 0.0f;

    for (int k0 = 0; k0 < DD; k0 += 16) {
        // Load A tile (64 rows x 16 k), one float4 per thread, store transposed.
        {
            const int r  = tid >> 2;            // 0..63
            const int c4 = (tid & 3) * 4;       // 0,4,8,12
            float4 a = *(const float4*)&x[(size_t)(bm + r) * DD + k0 + c4];
            As[c4 + 0][r] = a.x;
            As[c4 + 1][r] = a.y;
            As[c4 + 2][r] = a.z;
            As[c4 + 3][r] = a.w;
        }
        // Load B tile (16 k x 64 n), one float4 per thread.
        {
            const int r  = tid >> 4;            // 0..15
            const int c4 = (tid & 15) * 4;      // 0..60
            *(float4*)&Bs[r][c4] = *(const float4*)&w[(size_t)(k0 + r) * OO + bn + c4];
        }
        __syncthreads();

        #pragma unroll
        for (int k = 0; k < 16; k++) {
            float4 a = *(const float4*)&As[k][ty * 4];
            float4 b = *(const float4*)&Bs[k][tx * 4];
            float av[4] = {a.x, a.y, a.z, a.w};
            float bv[4] = {b.x, b.y, b.z, b.w};
            #pragma unroll
            for (int i = 0; i < 4; i++)
                #pragma unroll
                for (int j = 0; j < 4; j++)
                    acc[i][j] = fmaf(av[i], bv[j], acc[i][j]);
        }
        __syncthreads();
    }

    // Epilogue: + bias + bias_eps
    #pragma unroll
    for (int i = 0; i < 4; i++) {
        const int row = bm + ty * 4 + i;
        #pragma unroll
        for (int j = 0; j < 4; j++) {
            const int col = bn + tx * 4 + j;
            out[(size_t)row * OO + col] = acc[i][j] + bias[col] + bias_eps[(size_t)row * OO + col];
        }
    }
}

// ---------------------------------------------------------------------------
// Kernel B: eps stream  out[p,o] += sum_d x[p,d] * eps[p,d,o]
// One CTA per p, 128 threads, each thread owns a float4 of o (fully coalesced:
// each d-iteration the CTA reads eps[p,d,0:512] = 2KB contiguous).
// ---------------------------------------------------------------------------
__global__ __launch_bounds__(128)
void nes_eps_stream(const float* __restrict__ x,
                    const float4* __restrict__ eps4,
                    float4* __restrict__ out4) {
    __shared__ float xs[DD];

    const int p   = blockIdx.x;
    const int tid = threadIdx.x;      // 0..127

    // Load x[p, :] (512 floats) into smem: 128 threads x float4.
    ((float4*)xs)[tid] = ((const float4*)(x + (size_t)p * DD))[tid];
    __syncthreads();

    const float4* e = eps4 + (size_t)p * (DD * OO / 4) + tid;  // row stride = 128 float4

    float4 acc = make_float4(0.f, 0.f, 0.f, 0.f);

    #pragma unroll 8
    for (int d = 0; d < DD; d++) {
        float4 v = e[d * (OO / 4)];
        float xv = xs[d];
        acc.x = fmaf(xv, v.x, acc.x);
        acc.y = fmaf(xv, v.y, acc.y);
        acc.z = fmaf(xv, v.z, acc.z);
        acc.w = fmaf(xv, v.w, acc.w);
    }

    float4 o = out4[(size_t)p * (OO / 4) + tid];
    o.x += acc.x; o.y += acc.y; o.z += acc.z; o.w += acc.w;
    out4[(size_t)p * (OO / 4) + tid] = o;
}

// ---------------------------------------------------------------------------
// Launch
// inputs (metadata order): x [P,D], weight [D,O], bias [O],
//                          weight_eps [P,D,O], bias_eps [P,O]
// output: float32 [P,O]
// ---------------------------------------------------------------------------
extern "C" void kernel_launch(void* const* d_in, const int* in_sizes, int n_in,
                              void* d_out, int out_size) {
    const float* x        = (const float*)d_in[0];
    const float* w        = (const float*)d_in[1];
    const float* bias     = (const float*)d_in[2];
    const float* eps      = (const float*)d_in[3];
    const float* bias_eps = (const float*)d_in[4];
    float*       out      = (float*)d_out;

    (void)in_sizes; (void)n_in; (void)out_size;

    dim3 gridA(OO / 64, PP / 64);   // (8, 16)
    nes_base_gemm<<<gridA, 256>>>(x, w, bias, bias_eps, out);

    nes_eps_stream<<<PP, 128>>>(x, (const float4*)eps, (float4*)out);
}

// round 2
// speedup vs baseline: 1.1986x; 1.1986x over previous
#include <cuda_runtime.h>
#include <cuda_bf16.h>

// out[p,o] = sum_d x[p,d]*(W[d,o] + eps[p,d,o]) + bias[o] + bias_eps[p,o]
// P=1024, D=512, O=512, fp32.
//
// Strategy: HBM-bound on streaming eps (1.07 GB, read once). One merged grid:
//   - CTAs [0, 1024): stream eps for row p, write out = epsdot + bias + bias_eps
//   - CTAs [1024, 1280): tiled GEMM xw = x@W into static scratch (hidden under stream)
// Then a tiny combine kernel: out += xw.

#define PP 1024
#define DD 512
#define OO 512

#define GEMM_CTAS 256          // 32-row x 64-col tiles: (1024/32) * (512/64)

__device__ float g_xw[PP * OO];   // 2 MB static scratch (allowed: no runtime alloc)

// ---------------------------------------------------------------------------
// Merged kernel: 128 threads per CTA.
// ---------------------------------------------------------------------------
__global__ __launch_bounds__(128)
void nes_fused(const float* __restrict__ x,
               const float* __restrict__ w,
               const float* __restrict__ bias,
               const float* __restrict__ eps,
               const float* __restrict__ bias_eps,
               float* __restrict__ out) {
    const int bid = blockIdx.x;
    const int tid = threadIdx.x;   // 0..127

    if (bid < PP) {
        // ------------------ eps stream CTA: one row p ------------------
        __shared__ float xs[DD];
        const int p = bid;

        ((float4*)xs)[tid] = ((const float4*)(x + (size_t)p * DD))[tid];

        // Per-thread epilogue operands fetched up front (hide under stream).
        float4 b4  = ((const float4*)bias)[tid];
        float4 be4 = ((const float4*)(bias_eps + (size_t)p * OO))[tid];
        __syncthreads();

        const float4* e = (const float4*)(eps + (size_t)p * DD * OO) + tid;

        float4 acc = make_float4(0.f, 0.f, 0.f, 0.f);
        #pragma unroll 8
        for (int d = 0; d < DD; d++) {
            float4 v = e[d * (OO / 4)];
            float xv = xs[d];
            acc.x = fmaf(xv, v.x, acc.x);
            acc.y = fmaf(xv, v.y, acc.y);
            acc.z = fmaf(xv, v.z, acc.z);
            acc.w = fmaf(xv, v.w, acc.w);
        }

        float4 o;
        o.x = acc.x + b4.x + be4.x;
        o.y = acc.y + b4.y + be4.y;
        o.z = acc.z + b4.z + be4.z;
        o.w = acc.w + b4.w + be4.w;
        ((float4*)(out + (size_t)p * OO))[tid] = o;
    } else {
        // ------------------ GEMM CTA: 32x64 tile of xw = x @ W ------------------
        __shared__ float As[16][32];   // [k][m]
        __shared__ float Bs[16][64];   // [k][n]

        const int g  = bid - PP;
        const int bm = (g >> 3) * 32;          // p-tile (32 tiles of 32)
        const int bn = (g & 7) * 64;           // o-tile (8 tiles of 64)
        const int tx = tid & 15;               // n-group (16)
        const int ty = tid >> 4;               // m-group (8)

        float acc[4][4];
        #pragma unroll
        for (int i = 0; i < 4; i++)
            #pragma unroll
            for (int j = 0; j < 4; j++) acc[i][j] = 0.0f;

        for (int k0 = 0; k0 < DD; k0 += 16) {
            // A tile: 32 rows x 16 k. 128 threads x float4 = 512 floats.
            {
                const int r  = tid >> 2;           // 0..31
                const int c4 = (tid & 3) * 4;      // 0,4,8,12
                float4 a = *(const float4*)&x[(size_t)(bm + r) * DD + k0 + c4];
                As[c4 + 0][r] = a.x;
                As[c4 + 1][r] = a.y;
                As[c4 + 2][r] = a.z;
                As[c4 + 3][r] = a.w;
            }
            // B tile: 16 k x 64 n = 1024 floats = 256 float4, 2 per thread.
            {
                const int r  = tid >> 4;           // 0..7 (first half)
                const int c4 = (tid & 15) * 4;
                *(float4*)&Bs[r][c4]     = *(const float4*)&w[(size_t)(k0 + r) * OO + bn + c4];
                *(float4*)&Bs[r + 8][c4] = *(const float4*)&w[(size_t)(k0 + r + 8) * OO + bn + c4];
            }
            __syncthreads();

            #pragma unroll
            for (int k = 0; k < 16; k++) {
                float4 a = *(const float4*)&As[k][ty * 4];
                float4 b = *(const float4*)&Bs[k][tx * 4];
                float av[4] = {a.x, a.y, a.z, a.w};
                float bv[4] = {b.x, b.y, b.z, b.w};
                #pragma unroll
                for (int i = 0; i < 4; i++)
                    #pragma unroll
                    for (int j = 0; j < 4; j++)
                        acc[i][j] = fmaf(av[i], bv[j], acc[i][j]);
            }
            __syncthreads();
        }

        #pragma unroll
        for (int i = 0; i < 4; i++) {
            const int row = bm + ty * 4 + i;
            #pragma unroll
            for (int j = 0; j < 4; j++) {
                const int col = bn + tx * 4 + j;
                g_xw[(size_t)row * OO + col] = acc[i][j];
            }
        }
    }
}

// ---------------------------------------------------------------------------
// Combine: out += xw   (6 MB traffic, ~1.5us)
// ---------------------------------------------------------------------------
__global__ __launch_bounds__(256)
void nes_combine(float4* __restrict__ out4) {
    const int i = blockIdx.x * blockDim.x + threadIdx.x;   // 0 .. P*O/4-1
    const float4* xw4 = (const float4*)g_xw;
    float4 o = out4[i];
    float4 a = xw4[i];
    o.x += a.x; o.y += a.y; o.z += a.z; o.w += a.w;
    out4[i] = o;
}

// ---------------------------------------------------------------------------
// Launch
// inputs: x [P,D], weight [D,O], bias [O], weight_eps [P,D,O], bias_eps [P,O]
// ---------------------------------------------------------------------------
extern "C" void kernel_launch(void* const* d_in, const int* in_sizes, int n_in,
                              void* d_out, int out_size) {
    const float* x        = (const float*)d_in[0];
    const float* w        = (const float*)d_in[1];
    const float* bias     = (const float*)d_in[2];
    const float* eps      = (const float*)d_in[3];
    const float* bias_eps = (const float*)d_in[4];
    float*       out      = (float*)d_out;

    (void)in_sizes; (void)n_in; (void)out_size;

    nes_fused<<<PP + GEMM_CTAS, 128>>>(x, w, bias, eps, bias_eps, out);

    const int n4 = PP * OO / 4;               // 131072 float4
    nes_combine<<<n4 / 256, 256>>>((float4*)out);
}

// round 3
// speedup vs baseline: 1.2071x; 1.0071x over previous
#include <cuda_runtime.h>
#include <cuda_bf16.h>

// out[p,o] = sum_d x[p,d]*(W[d,o] + eps[p,d,o]) + bias[o] + bias_eps[p,o]
// P=1024, D=512, O=512, fp32.
//
// Single merged grid, single kernel:
//   - CTAs [0, 1024): stream eps for row p (~150us, HBM-bound)
//   - CTAs [1024, 1280): tiled GEMM xw = x@W into static scratch (~20us, hidden)
// Stream CTAs consume xw AFTER their stream loop via a device-wide spin-flag
// (all 1280 CTAs are co-resident in one wave -> no deadlock; GEMM finishes
// long before any stream CTA reaches the gate, so no real spinning).
// Counters self-reset each launch -> graph-replay deterministic.

#define PP 1024
#define DD 512
#define OO 512
#define GEMM_CTAS 256          // (1024/32 rows) * (512/64 cols)

__device__ float g_xw[PP * OO];        // 2 MB scratch (static, no runtime alloc)
__device__ int   g_done = 0;           // GEMM CTAs completed
__device__ int   g_stream_done = 0;    // stream CTAs past the gate

__global__ __launch_bounds__(128)
void nes_fused(const float* __restrict__ x,
               const float* __restrict__ w,
               const float* __restrict__ bias,
               const float* __restrict__ eps,
               const float* __restrict__ bias_eps,
               float* __restrict__ out) {
    const int bid = blockIdx.x;
    const int tid = threadIdx.x;   // 0..127

    if (bid < PP) {
        // ------------------ eps stream CTA: one row p ------------------
        __shared__ float xs[DD];
        const int p = bid;

        ((float4*)xs)[tid] = ((const float4*)(x + (size_t)p * DD))[tid];

        // Epilogue operands fetched up front (latency hidden under the stream).
        float4 b4  = ((const float4*)bias)[tid];
        float4 be4 = ((const float4*)(bias_eps + (size_t)p * OO))[tid];
        __syncthreads();

        const float4* e = (const float4*)(eps + (size_t)p * DD * OO) + tid;

        float4 acc = make_float4(0.f, 0.f, 0.f, 0.f);
        #pragma unroll 8
        for (int d = 0; d < DD; d++) {
            float4 v = e[d * (OO / 4)];
            float xv = xs[d];
            acc.x = fmaf(xv, v.x, acc.x);
            acc.y = fmaf(xv, v.y, acc.y);
            acc.z = fmaf(xv, v.z, acc.z);
            acc.w = fmaf(xv, v.w, acc.w);
        }

        // ---- gate: wait for all GEMM CTAs (in practice already done) ----
        if (tid == 0) {
            while (atomicAdd(&g_done, 0) < GEMM_CTAS) { }
        }
        __syncthreads();
        __threadfence();   // acquire: order g_xw reads after the flag

        float4 xw = ((const float4*)(g_xw + (size_t)p * OO))[tid];

        float4 o;
        o.x = acc.x + xw.x + b4.x + be4.x;
        o.y = acc.y + xw.y + b4.y + be4.y;
        o.z = acc.z + xw.z + b4.z + be4.z;
        o.w = acc.w + xw.w + b4.w + be4.w;
        ((float4*)(out + (size_t)p * OO))[tid] = o;

        // ---- self-reset for next graph replay ----
        if (tid == 0) {
            int old = atomicAdd(&g_stream_done, 1);
            if (old == PP - 1) {
                // All stream CTAs have passed the gate; safe to reset.
                atomicExch(&g_stream_done, 0);
                atomicExch(&g_done, 0);
            }
        }
    } else {
        // ------------------ GEMM CTA: 32x64 tile of xw = x @ W ------------------
        __shared__ float As[16][32];   // [k][m]
        __shared__ float Bs[16][64];   // [k][n]

        const int g  = bid - PP;
        const int bm = (g >> 3) * 32;
        const int bn = (g & 7) * 64;
        const int tx = tid & 15;
        const int ty = tid >> 4;

        float acc[4][4];
        #pragma unroll
        for (int i = 0; i < 4; i++)
            #pragma unroll
            for (int j = 0; j < 4; j++) acc[i][j] = 0.0f;

        for (int k0 = 0; k0 < DD; k0 += 16) {
            {
                const int r  = tid >> 2;
                const int c4 = (tid & 3) * 4;
                float4 a = *(const float4*)&x[(size_t)(bm + r) * DD + k0 + c4];
                As[c4 + 0][r] = a.x;
                As[c4 + 1][r] = a.y;
                As[c4 + 2][r] = a.z;
                As[c4 + 3][r] = a.w;
            }
            {
                const int r  = tid >> 4;           // 0..7
                const int c4 = (tid & 15) * 4;
                *(float4*)&Bs[r][c4]     = *(const float4*)&w[(size_t)(k0 + r) * OO + bn + c4];
                *(float4*)&Bs[r + 8][c4] = *(const float4*)&w[(size_t)(k0 + r + 8) * OO + bn + c4];
            }
            __syncthreads();

            #pragma unroll
            for (int k = 0; k < 16; k++) {
                float4 a = *(const float4*)&As[k][ty * 4];
                float4 b = *(const float4*)&Bs[k][tx * 4];
                float av[4] = {a.x, a.y, a.z, a.w};
                float bv[4] = {b.x, b.y, b.z, b.w};
                #pragma unroll
                for (int i = 0; i < 4; i++)
                    #pragma unroll
                    for (int j = 0; j < 4; j++)
                        acc[i][j] = fmaf(av[i], bv[j], acc[i][j]);
            }
            __syncthreads();
        }

        #pragma unroll
        for (int i = 0; i < 4; i++) {
            const int row = bm + ty * 4 + i;
            #pragma unroll
            for (int j = 0; j < 4; j++) {
                const int col = bn + tx * 4 + j;
                g_xw[(size_t)row * OO + col] = acc[i][j];
            }
        }

        __threadfence();   // release: publish g_xw before the flag
        __syncthreads();
        if (tid == 0) atomicAdd(&g_done, 1);
    }
}

extern "C" void kernel_launch(void* const* d_in, const int* in_sizes, int n_in,
                              void* d_out, int out_size) {
    const float* x        = (const float*)d_in[0];
    const float* w        = (const float*)d_in[1];
    const float* bias     = (const float*)d_in[2];
    const float* eps      = (const float*)d_in[3];
    const float* bias_eps = (const float*)d_in[4];
    float*       out      = (float*)d_out;

    (void)in_sizes; (void)n_in; (void)out_size;

    nes_fused<<<PP + GEMM_CTAS, 128>>>(x, w, bias, eps, bias_eps, out);
}

// round 6
// speedup vs baseline: 1.2262x; 1.0158x over previous
#include <cuda_runtime.h>
#include <cuda_bf16.h>

// out[p,o] = sum_d x[p,d]*(W[d,o] + eps[p,d,o]) + bias[o] + bias_eps[p,o]
// P=1024, D=512, O=512, fp32.
//
// Single kernel, 1280 CTAs:
//   - CTAs [0, 256): tiled GEMM xw = x@W into static scratch (~15-20us)
//     Placed FIRST in the grid: scheduled/retired earliest, which both shrinks
//     the interference window on the stream and makes the spin-gate
//     deadlock-free under any occupancy.
//   - CTAs [256, 1280): stream eps for row p (~150us, HBM-bound), then gate on
//     the GEMM flag (already set by then) and write the final out row.
// eps reads use evict-first (.cs): pure streaming data, keep L2 for W/x/g_xw.
// out written with .cs (write-once). Counters self-reset each launch ->
// graph-replay deterministic.

#define PP 1024
#define DD 512
#define OO 512
#define GEMM_CTAS 256          // (1024/32 rows) * (512/64 cols)

__device__ float g_xw[PP * OO];        // 2 MB scratch (static, no runtime alloc)
__device__ int   g_done = 0;           // GEMM CTAs completed
__device__ int   g_stream_done = 0;    // stream CTAs past the gate

__global__ __launch_bounds__(128)
void nes_fused(const float* __restrict__ x,
               const float* __restrict__ w,
               const float* __restrict__ bias,
               const float* __restrict__ eps,
               const float* __restrict__ bias_eps,
               float* __restrict__ out) {
    const int bid = blockIdx.x;
    const int tid = threadIdx.x;   // 0..127

    if (bid >= GEMM_CTAS) {
        // ------------------ eps stream CTA: one row p ------------------
        __shared__ float xs[DD];
        const int p = bid - GEMM_CTAS;

        ((float4*)xs)[tid] = ((const float4*)(x + (size_t)p * DD))[tid];

        // Epilogue operands fetched up front (latency hidden under the stream).
        float4 b4  = ((const float4*)bias)[tid];
        float4 be4 = ((const float4*)(bias_eps + (size_t)p * OO))[tid];
        __syncthreads();

        const float4* e = (const float4*)(eps + (size_t)p * DD * OO) + tid;

        float4 acc = make_float4(0.f, 0.f, 0.f, 0.f);
        #pragma unroll 8
        for (int d = 0; d < DD; d++) {
            float4 v = __ldcs(&e[d * (OO / 4)]);   // evict-first: pure stream
            float xv = xs[d];
            acc.x = fmaf(xv, v.x, acc.x);
            acc.y = fmaf(xv, v.y, acc.y);
            acc.z = fmaf(xv, v.z, acc.z);
            acc.w = fmaf(xv, v.w, acc.w);
        }

        // ---- gate: wait for all GEMM CTAs (in practice already done) ----
        if (tid == 0) {
            while (atomicAdd(&g_done, 0) < GEMM_CTAS) { }
        }
        __syncthreads();
        __threadfence();   // acquire: order g_xw reads after the flag

        float4 xw = ((const float4*)(g_xw + (size_t)p * OO))[tid];

        float4 o;
        o.x = acc.x + xw.x + b4.x + be4.x;
        o.y = acc.y + xw.y + b4.y + be4.y;
        o.z = acc.z + xw.z + b4.z + be4.z;
        o.w = acc.w + xw.w + b4.w + be4.w;
        __stcs(&((float4*)(out + (size_t)p * OO))[tid], o);   // write-once stream

        // ---- self-reset for next graph replay ----
        if (tid == 0) {
            int old = atomicAdd(&g_stream_done, 1);
            if (old == PP - 1) {
                // All stream CTAs have passed the gate; safe to reset.
                atomicExch(&g_stream_done, 0);
                atomicExch(&g_done, 0);
            }
        }
    } else {
        // ------------------ GEMM CTA: 32x64 tile of xw = x @ W ------------------
        __shared__ float As[16][32];   // [k][m]
        __shared__ float Bs[16][64];   // [k][n]

        const int g  = bid;
        const int bm = (g >> 3) * 32;
        const int bn = (g & 7) * 64;
        const int tx = tid & 15;
        const int ty = tid >> 4;

        float acc[4][4];
        #pragma unroll
        for (int i = 0; i < 4; i++)
            #pragma unroll
            for (int j = 0; j < 4; j++) acc[i][j] = 0.0f;

        for (int k0 = 0; k0 < DD; k0 += 16) {
            {
                const int r  = tid >> 2;
                const int c4 = (tid & 3) * 4;
                float4 a = *(const float4*)&x[(size_t)(bm + r) * DD + k0 + c4];
                As[c4 + 0][r] = a.x;
                As[c4 + 1][r] = a.y;
                As[c4 + 2][r] = a.z;
                As[c4 + 3][r] = a.w;
            }
            {
                const int r  = tid >> 4;           // 0..7
                const int c4 = (tid & 15) * 4;
                *(float4*)&Bs[r][c4]     = *(const float4*)&w[(size_t)(k0 + r) * OO + bn + c4];
                *(float4*)&Bs[r + 8][c4] = *(const float4*)&w[(size_t)(k0 + r + 8) * OO + bn + c4];
            }
            __syncthreads();

            #pragma unroll
            for (int k = 0; k < 16; k++) {
                float4 a = *(const float4*)&As[k][ty * 4];
                float4 b = *(const float4*)&Bs[k][tx * 4];
                float av[4] = {a.x, a.y, a.z, a.w};
                float bv[4] = {b.x, b.y, b.z, b.w};
                #pragma unroll
                for (int i = 0; i < 4; i++)
                    #pragma unroll
                    for (int j = 0; j < 4; j++)
                        acc[i][j] = fmaf(av[i], bv[j], acc[i][j]);
            }
            __syncthreads();
        }

        #pragma unroll
        for (int i = 0; i < 4; i++) {
            const int row = bm + ty * 4 + i;
            #pragma unroll
            for (int j = 0; j < 4; j++) {
                const int col = bn + tx * 4 + j;
                g_xw[(size_t)row * OO + col] = acc[i][j];
            }
        }

        __threadfence();   // release: publish g_xw before the flag
        __syncthreads();
        if (tid == 0) atomicAdd(&g_done, 1);
    }
}

extern "C" void kernel_launch(void* const* d_in, const int* in_sizes, int n_in,
                              void* d_out, int out_size) {
    const float* x        = (const float*)d_in[0];
    const float* w        = (const float*)d_in[1];
    const float* bias     = (const float*)d_in[2];
    const float* eps      = (const float*)d_in[3];
    const float* bias_eps = (const float*)d_in[4];
    float*       out      = (float*)d_out;

    (void)in_sizes; (void)n_in; (void)out_size;

    nes_fused<<<PP + GEMM_CTAS, 128>>>(x, w, bias, eps, bias_eps, out);
}